// round 13
// baseline (speedup 1.0000x reference)
#include <cuda_runtime.h>
#include <cuda_fp16.h>
#include <math.h>
#include <stdint.h>

#define DINLINE __device__ __forceinline__

// Problem constants: B=16, C=256, H=W=64, K=7, C/4=64, C*K*K=12544

// ---- scratch (static device allocations: allowed) ----
__device__ __align__(128) float g_pooled[16 * 256];            // [B, C]
__device__ __align__(128) float g_h[16 * 64];                  // [B, C/4]
__device__ __align__(128) float g_fused[16 * 256 * 49];        // [B, C, 49]
__device__ __align__(128) __half g_bh[16u*256u*64u*64u];       // dw out, fp16 (32 MB)
__device__ __align__(128) __half g_pwh[256 * 256];             // fp16 pw weights

// ===========================================================================
// PTX helpers (all legal on plain sm_100 target)
// ===========================================================================
DINLINE uint32_t smem_u32(const void* p) {
    uint32_t a;
    asm("{ .reg .u64 t; cvta.to.shared.u64 t, %1; cvt.u32.u64 %0, t; }" : "=r"(a) : "l"(p));
    return a;
}
DINLINE void ldsm_x4(uint32_t* r, uint32_t addr) {
    asm volatile("ldmatrix.sync.aligned.m8n8.x4.shared.b16 {%0,%1,%2,%3}, [%4];"
                 : "=r"(r[0]), "=r"(r[1]), "=r"(r[2]), "=r"(r[3]) : "r"(addr));
}
DINLINE void ldsm_x4_t(uint32_t* r, uint32_t addr) {
    asm volatile("ldmatrix.sync.aligned.m8n8.x4.trans.shared.b16 {%0,%1,%2,%3}, [%4];"
                 : "=r"(r[0]), "=r"(r[1]), "=r"(r[2]), "=r"(r[3]) : "r"(addr));
}
DINLINE void mma_f16(float* d, const uint32_t* a, const uint32_t* b) {
    asm volatile(
        "mma.sync.aligned.m16n8k16.row.col.f32.f16.f16.f32 "
        "{%0,%1,%2,%3}, {%4,%5,%6,%7}, {%8,%9}, {%0,%1,%2,%3};"
        : "+f"(d[0]), "+f"(d[1]), "+f"(d[2]), "+f"(d[3])
        : "r"(a[0]), "r"(a[1]), "r"(a[2]), "r"(a[3]), "r"(b[0]), "r"(b[1]));
}
DINLINE void cp16(uint32_t dst, const void* src) {
    asm volatile("cp.async.cg.shared.global [%0], [%1], 16;"
                 :: "r"(dst), "l"(__cvta_generic_to_global(src)));
}
DINLINE void cp_commit() { asm volatile("cp.async.commit_group;" ::: "memory"); }
DINLINE void cp_wait0()  { asm volatile("cp.async.wait_group 0;" ::: "memory"); }
DINLINE void cp_wait1()  { asm volatile("cp.async.wait_group 1;" ::: "memory"); }

// ---------------------------------------------------------------------------
// Kernel 1: global average pool (+ pw fp16 convert folded into first 256 blocks)
// ---------------------------------------------------------------------------
__global__ void pool_kernel(const float* __restrict__ x, const float* __restrict__ pw) {
    int bc = blockIdx.x;
    if (bc < 256) {
        int i = bc * 256 + threadIdx.x;
        g_pwh[i] = __float2half_rn(pw[i]);
    }
    const float4* xp = (const float4*)(x + (size_t)bc * 4096);
    float s = 0.f;
    #pragma unroll 4
    for (int i = threadIdx.x; i < 1024; i += 256) {
        float4 v = xp[i];
        s += (v.x + v.y) + (v.z + v.w);
    }
    __shared__ float red[256];
    red[threadIdx.x] = s;
    __syncthreads();
    for (int off = 128; off > 0; off >>= 1) {
        if (threadIdx.x < off) red[threadIdx.x] += red[threadIdx.x + off];
        __syncthreads();
    }
    if (threadIdx.x == 0) g_pooled[bc] = red[0] * (1.f / 4096.f);
}

// ---------------------------------------------------------------------------
// Kernel 2: h = gelu(pooled @ w1^T + b1)
// ---------------------------------------------------------------------------
__global__ void mlp1_kernel(const float* __restrict__ w1, const float* __restrict__ b1) {
    int b = blockIdx.x;
    int j = threadIdx.x;   // 0..63
    __shared__ float p[256];
    for (int i = threadIdx.x; i < 256; i += 64) p[i] = g_pooled[b * 256 + i];
    __syncthreads();
    float s = b1[j];
    const float* wr = w1 + (size_t)j * 256;
    #pragma unroll 8
    for (int c = 0; c < 256; c++) s += p[c] * wr[c];
    g_h[b * 64 + j] = 0.5f * s * (1.0f + erff(s * 0.70710678118654752f));
}

// ---------------------------------------------------------------------------
// Kernel 3: fused[b,wi] = dw[wi] + b2[wi] + sum_j h[b,j]*w2[wi,j]
// ---------------------------------------------------------------------------
__global__ void __launch_bounds__(256) fuse_kernel(const float* __restrict__ dw,
                                                   const float* __restrict__ w2,
                                                   const float* __restrict__ b2) {
    __shared__ float hs[8 * 64];
    __shared__ float w2s[128 * 68];
    int tid = threadIdx.x;
    int wi0 = blockIdx.x * 128;
    int b0 = blockIdx.y * 8;

    if (tid < 128) *(float4*)(hs + tid * 4) = *(const float4*)(g_h + b0 * 64 + tid * 4);
    #pragma unroll
    for (int i = 0; i < 8; i++) {
        int lin = tid + i * 256;
        int r = lin >> 4, j4 = lin & 15;
        float4 v = *(const float4*)(w2 + (size_t)(wi0 + r) * 64 + j4 * 4);
        *(float4*)(w2s + r * 68 + j4 * 4) = v;
    }
    __syncthreads();

    int wiL = tid & 127;
    int bg = (tid >> 7) * 4;
    int wi = wi0 + wiL;
    float base = dw[wi] + b2[wi];
    float acc[4];
    #pragma unroll
    for (int bb = 0; bb < 4; bb++) acc[bb] = base;

    const float* wr = w2s + wiL * 68;
    #pragma unroll
    for (int j4 = 0; j4 < 16; j4++) {
        float4 w = *(const float4*)(wr + j4 * 4);
        #pragma unroll
        for (int bb = 0; bb < 4; bb++) {
            float4 h = *(const float4*)(hs + (bg + bb) * 64 + j4 * 4);
            acc[bb] += w.x * h.x + w.y * h.y + w.z * h.z + w.w * h.w;
        }
    }
    #pragma unroll
    for (int bb = 0; bb < 4; bb++)
        g_fused[(size_t)(b0 + bg + bb) * 12544 + wi] = acc[bb];
}

// ---------------------------------------------------------------------------
// Kernel 4: per-sample depthwise 7x7 conv, pad=3.  (unchanged R11 winner)
// Block = 32-row tile; thread = 2 rows x 4 cols (8 outputs).
// ---------------------------------------------------------------------------
__global__ void __launch_bounds__(256, 2) dw_kernel(const float* __restrict__ x) {
    int bc = blockIdx.y;
    int rowBase = blockIdx.x * 32;
    const float* xp = x + (size_t)bc * 4096;

    __shared__ __align__(16) float s[38 * 70];
    __shared__ float wsh[49];

    if (threadIdx.x < 49) wsh[threadIdx.x] = g_fused[bc * 49 + threadIdx.x];

    for (int i = threadIdx.x; i < 38 * 70; i += 256) {
        int r = i / 70, cc = i - r * 70;
        int gr = rowBase + r - 3, gc = cc - 3;
        s[i] = (gr >= 0 && gr < 64 && gc >= 0 && gc < 64) ? xp[gr * 64 + gc] : 0.f;
    }
    __syncthreads();

    float w[49];
    #pragma unroll
    for (int q = 0; q < 49; q++) w[q] = wsh[q];
    #pragma unroll
    for (int q = 0; q < 49; q++) asm volatile("" : "+f"(w[q]));

    const int c0  = (threadIdx.x & 15) * 4;
    const int lr0 = (threadIdx.x >> 4) * 2;

    float acc0[4] = {0.f, 0.f, 0.f, 0.f};
    float acc1[4] = {0.f, 0.f, 0.f, 0.f};

    #pragma unroll
    for (int r = 0; r < 8; r++) {
        float v[10];
        const float* row = s + (lr0 + r) * 70 + c0;
        #pragma unroll
        for (int q = 0; q < 5; q++) *(float2*)&v[q * 2] = *(const float2*)(row + q * 2);

        if (r <= 6) {
            #pragma unroll
            for (int kx = 0; kx < 7; kx++) {
                float wv = w[r * 7 + kx];
                #pragma unroll
                for (int c = 0; c < 4; c++) acc0[c] += v[kx + c] * wv;
            }
        }
        if (r >= 1) {
            #pragma unroll
            for (int kx = 0; kx < 7; kx++) {
                float wv = w[(r - 1) * 7 + kx];
                #pragma unroll
                for (int c = 0; c < 4; c++) acc1[c] += v[kx + c] * wv;
            }
        }
    }

    uint32_t base = (uint32_t)bc * 4096u + (uint32_t)(rowBase + lr0) * 64u + (uint32_t)c0;
    {
        __half2 ha, hb;
        ha.x = __float2half_rn(acc0[0]); ha.y = __float2half_rn(acc0[1]);
        hb.x = __float2half_rn(acc0[2]); hb.y = __float2half_rn(acc0[3]);
        uint2 st; st.x = *(uint32_t*)&ha; st.y = *(uint32_t*)&hb;
        *(uint2*)&g_bh[base] = st;
    }
    {
        __half2 ha, hb;
        ha.x = __float2half_rn(acc1[0]); ha.y = __float2half_rn(acc1[1]);
        hb.x = __float2half_rn(acc1[2]); hb.y = __float2half_rn(acc1[3]);
        uint2 st; st.x = *(uint32_t*)&ha; st.y = *(uint32_t*)&hb;
        *(uint2*)&g_bh[base + 64] = st;
    }
}

// ---------------------------------------------------------------------------
// Kernel 5: pointwise GEMM, fp16 mma single pass.
// 2-stage pipeline (36.9KB) + __launch_bounds__(256,2) => 2 CTAs/SM,
// smem-staged coalesced epilogue with 132-float row pitch (16B-aligned rows).
//   Stage (18432 B): A[128x80B] @0, B[32x256B] @10240.
// ---------------------------------------------------------------------------
__global__ void __launch_bounds__(256, 2) pw_gemm_mma(float* __restrict__ out) {
    extern __shared__ __align__(128) char sm[];
    const uint32_t smb = smem_u32(sm);
    const uint32_t STAGE = 18432;

    const int tid = threadIdx.x;
    const int wid = tid >> 5, lane = tid & 31;
    const int warp_m = wid & 1;
    const int warp_n = wid >> 1;
    const int n0 = blockIdx.x * 128;
    const int m0 = blockIdx.y * 128;
    const int b  = blockIdx.z;

    float acc[4][4][4];
    #pragma unroll
    for (int i = 0; i < 4; i++)
        #pragma unroll
        for (int j = 0; j < 4; j++)
            #pragma unroll
            for (int q = 0; q < 4; q++) acc[i][j][q] = 0.f;

    const int lm16 = lane & 15, lhi = lane >> 4;
    const uint32_t aRowOff = (uint32_t)(warp_m * 64 + lm16) * 80 + (uint32_t)lhi * 16;
    const int bN = warp_n * 32 + lhi * 8;

    float* ob = out + (size_t)b * 1048576;

    auto issue = [&](int kc, uint32_t sbase) {
        #pragma unroll
        for (int i = 0; i < 2; i++) {
            int lin = tid + i * 256;
            int r = lin >> 2, j = lin & 3;
            const __half* src = g_pwh + (size_t)(m0 + r) * 256 + kc * 32 + j * 8;
            cp16(sbase + r * 80 + j * 16, src);
        }
        #pragma unroll
        for (int i = 0; i < 2; i++) {
            int lin = tid + i * 256;
            int k = lin >> 4, j16 = lin & 15;
            const __half* src = g_bh + (size_t)b * 1048576
                + (size_t)(kc * 32 + k) * 4096 + n0 + j16 * 8;
            cp16(sbase + 10240 + (uint32_t)k * 256
                 + (uint32_t)((j16 ^ (k & 7)) * 16), src);
        }
        cp_commit();
    };

    issue(0, smb);
    issue(1, smb + STAGE);

    for (int kc = 0; kc < 8; kc++) {
        const uint32_t sbase = smb + (uint32_t)(kc & 1) * STAGE;
        if (kc == 7) cp_wait0(); else cp_wait1();
        __syncthreads();                          // stage kc ready

        const uint32_t aB = sbase, bB = sbase + 10240;
        #pragma unroll
        for (int ks = 0; ks < 2; ks++) {
            uint32_t bf[2][4];
            #pragma unroll
            for (int p = 0; p < 2; p++) {
                int k = ks * 16 + lm16;
                int n = bN + p * 16;
                uint32_t off = (uint32_t)k * 256
                             + (uint32_t)(((n >> 3) ^ (k & 7)) * 16);
                ldsm_x4_t(bf[p], bB + off);
            }
            uint32_t af[4][4];
            #pragma unroll
            for (int mi = 0; mi < 4; mi++)
                ldsm_x4(af[mi], aB + aRowOff + (uint32_t)mi * (16 * 80)
                               + (uint32_t)ks * 32);
            #pragma unroll
            for (int mi = 0; mi < 4; mi++) {
                #pragma unroll
                for (int p = 0; p < 2; p++) {
                    mma_f16(acc[mi][2 * p],     af[mi], &bf[p][0]);
                    mma_f16(acc[mi][2 * p + 1], af[mi], &bf[p][2]);
                }
            }
        }

        if (kc < 6) {
            __syncthreads();                      // all warps done with stage kc&1
            issue(kc + 2, sbase);                 // refill same stage
        }
    }

    // ---- smem-staged coalesced epilogue (132-float pitch: rows 16B aligned) ----
    float* cs = (float*)sm;                       // [64][132] padded fp32 = 33792 B
    #pragma unroll
    for (int half = 0; half < 2; half++) {
        __syncthreads();
        if (warp_m == half) {
            #pragma unroll
            for (int mi = 0; mi < 4; mi++) {
                int rr = (lane >> 2) + mi * 16;
                #pragma unroll
                for (int ni = 0; ni < 4; ni++) {
                    int cc = warp_n * 32 + (lane & 3) * 2 + ni * 8;
                    *(float2*)&cs[rr * 132 + cc] =
                        make_float2(acc[mi][ni][0], acc[mi][ni][1]);
                    *(float2*)&cs[(rr + 8) * 132 + cc] =
                        make_float2(acc[mi][ni][2], acc[mi][ni][3]);
                }
            }
        }
        __syncthreads();
        // each warp writes full 512B row segments: rows wid, wid+8, ..., wid+56
        #pragma unroll
        for (int rr8 = 0; rr8 < 8; rr8++) {
            int row = wid + rr8 * 8;
            float4 v = *(float4*)&cs[row * 132 + lane * 4];
            *(float4*)&ob[(size_t)(m0 + half * 64 + row) * 4096 + n0 + lane * 4] = v;
        }
    }
}

// ---------------------------------------------------------------------------
// launch
// ---------------------------------------------------------------------------
extern "C" void kernel_launch(void* const* d_in, const int* in_sizes, int n_in,
                              void* d_out, int out_size) {
    const float* x   = (const float*)d_in[0];  // [16,256,64,64]
    const float* dw  = (const float*)d_in[1];  // [256,1,7,7]
    const float* pwm = (const float*)d_in[2];  // [256,256]
    const float* w1  = (const float*)d_in[3];  // [64,256]
    const float* b1  = (const float*)d_in[4];  // [64]
    const float* w2  = (const float*)d_in[5];  // [12544,64]
    const float* b2  = (const float*)d_in[6];  // [12544]
    float* out = (float*)d_out;                // [16,256,64,64] fp32

    cudaFuncSetAttribute(pw_gemm_mma, cudaFuncAttributeMaxDynamicSharedMemorySize, 36864);

    pool_kernel<<<4096, 256>>>(x, pwm);
    mlp1_kernel<<<16, 64>>>(w1, b1);
    fuse_kernel<<<dim3(98, 2), 256>>>(dw, w2, b2);
    dw_kernel<<<dim3(2, 4096), 256>>>(x);
    pw_gemm_mma<<<dim3(32, 2, 16), 256, 36864>>>(out);
}

// round 14
// speedup vs baseline: 1.3378x; 1.3378x over previous
#include <cuda_runtime.h>
#include <cuda_fp16.h>
#include <math.h>
#include <stdint.h>

#define DINLINE __device__ __forceinline__

// Problem constants: B=16, C=256, H=W=64, K=7, C/4=64, C*K*K=12544

// ---- scratch (static device allocations: allowed) ----
__device__ __align__(128) float g_pooled[16 * 256];            // [B, C]
__device__ __align__(128) float g_h[16 * 64];                  // [B, C/4]
__device__ __align__(128) float g_fused[16 * 256 * 49];        // [B, C, 49]
__device__ __align__(128) __half g_bh[16u*256u*64u*64u];       // dw out, fp16 (32 MB)
__device__ __align__(128) __half g_pwh[256 * 256];             // fp16 pw weights

// ===========================================================================
// PTX helpers (all legal on plain sm_100 target)
// ===========================================================================
DINLINE uint32_t smem_u32(const void* p) {
    uint32_t a;
    asm("{ .reg .u64 t; cvta.to.shared.u64 t, %1; cvt.u32.u64 %0, t; }" : "=r"(a) : "l"(p));
    return a;
}
DINLINE void ldsm_x4(uint32_t* r, uint32_t addr) {
    asm volatile("ldmatrix.sync.aligned.m8n8.x4.shared.b16 {%0,%1,%2,%3}, [%4];"
                 : "=r"(r[0]), "=r"(r[1]), "=r"(r[2]), "=r"(r[3]) : "r"(addr));
}
DINLINE void ldsm_x4_t(uint32_t* r, uint32_t addr) {
    asm volatile("ldmatrix.sync.aligned.m8n8.x4.trans.shared.b16 {%0,%1,%2,%3}, [%4];"
                 : "=r"(r[0]), "=r"(r[1]), "=r"(r[2]), "=r"(r[3]) : "r"(addr));
}
DINLINE void mma_f16(float* d, const uint32_t* a, const uint32_t* b) {
    asm volatile(
        "mma.sync.aligned.m16n8k16.row.col.f32.f16.f16.f32 "
        "{%0,%1,%2,%3}, {%4,%5,%6,%7}, {%8,%9}, {%0,%1,%2,%3};"
        : "+f"(d[0]), "+f"(d[1]), "+f"(d[2]), "+f"(d[3])
        : "r"(a[0]), "r"(a[1]), "r"(a[2]), "r"(a[3]), "r"(b[0]), "r"(b[1]));
}
DINLINE void cp16(uint32_t dst, const void* src) {
    asm volatile("cp.async.cg.shared.global [%0], [%1], 16;"
                 :: "r"(dst), "l"(__cvta_generic_to_global(src)));
}
DINLINE void cp_commit() { asm volatile("cp.async.commit_group;" ::: "memory"); }
DINLINE void cp_wait0()  { asm volatile("cp.async.wait_group 0;" ::: "memory"); }
DINLINE void cp_wait1()  { asm volatile("cp.async.wait_group 1;" ::: "memory"); }

// ---------------------------------------------------------------------------
// Kernel 1: global average pool (+ pw fp16 convert folded into first 256 blocks)
// ---------------------------------------------------------------------------
__global__ void pool_kernel(const float* __restrict__ x, const float* __restrict__ pw) {
    int bc = blockIdx.x;
    if (bc < 256) {
        int i = bc * 256 + threadIdx.x;
        g_pwh[i] = __float2half_rn(pw[i]);
    }
    const float4* xp = (const float4*)(x + (size_t)bc * 4096);
    float s = 0.f;
    #pragma unroll 4
    for (int i = threadIdx.x; i < 1024; i += 256) {
        float4 v = xp[i];
        s += (v.x + v.y) + (v.z + v.w);
    }
    __shared__ float red[256];
    red[threadIdx.x] = s;
    __syncthreads();
    for (int off = 128; off > 0; off >>= 1) {
        if (threadIdx.x < off) red[threadIdx.x] += red[threadIdx.x + off];
        __syncthreads();
    }
    if (threadIdx.x == 0) g_pooled[bc] = red[0] * (1.f / 4096.f);
}

// ---------------------------------------------------------------------------
// Kernel 2: h = gelu(pooled @ w1^T + b1)
// ---------------------------------------------------------------------------
__global__ void mlp1_kernel(const float* __restrict__ w1, const float* __restrict__ b1) {
    int b = blockIdx.x;
    int j = threadIdx.x;   // 0..63
    __shared__ float p[256];
    for (int i = threadIdx.x; i < 256; i += 64) p[i] = g_pooled[b * 256 + i];
    __syncthreads();
    float s = b1[j];
    const float* wr = w1 + (size_t)j * 256;
    #pragma unroll 8
    for (int c = 0; c < 256; c++) s += p[c] * wr[c];
    g_h[b * 64 + j] = 0.5f * s * (1.0f + erff(s * 0.70710678118654752f));
}

// ---------------------------------------------------------------------------
// Kernel 3: fused[b,wi] = dw[wi] + b2[wi] + sum_j h[b,j]*w2[wi,j]
// ---------------------------------------------------------------------------
__global__ void __launch_bounds__(256) fuse_kernel(const float* __restrict__ dw,
                                                   const float* __restrict__ w2,
                                                   const float* __restrict__ b2) {
    __shared__ float hs[8 * 64];
    __shared__ float w2s[128 * 68];
    int tid = threadIdx.x;
    int wi0 = blockIdx.x * 128;
    int b0 = blockIdx.y * 8;

    if (tid < 128) *(float4*)(hs + tid * 4) = *(const float4*)(g_h + b0 * 64 + tid * 4);
    #pragma unroll
    for (int i = 0; i < 8; i++) {
        int lin = tid + i * 256;
        int r = lin >> 4, j4 = lin & 15;
        float4 v = *(const float4*)(w2 + (size_t)(wi0 + r) * 64 + j4 * 4);
        *(float4*)(w2s + r * 68 + j4 * 4) = v;
    }
    __syncthreads();

    int wiL = tid & 127;
    int bg = (tid >> 7) * 4;
    int wi = wi0 + wiL;
    float base = dw[wi] + b2[wi];
    float acc[4];
    #pragma unroll
    for (int bb = 0; bb < 4; bb++) acc[bb] = base;

    const float* wr = w2s + wiL * 68;
    #pragma unroll
    for (int j4 = 0; j4 < 16; j4++) {
        float4 w = *(const float4*)(wr + j4 * 4);
        #pragma unroll
        for (int bb = 0; bb < 4; bb++) {
            float4 h = *(const float4*)(hs + (bg + bb) * 64 + j4 * 4);
            acc[bb] += w.x * h.x + w.y * h.y + w.z * h.z + w.w * h.w;
        }
    }
    #pragma unroll
    for (int bb = 0; bb < 4; bb++)
        g_fused[(size_t)(b0 + bg + bb) * 12544 + wi] = acc[bb];
}

// ---------------------------------------------------------------------------
// Kernel 4 v3: per-sample depthwise 7x7 conv, pad=3.
// Thread = 2 rows x 4 cols.  No weight pinning: 2-row weight double buffer
// (16 regs).  Loader: halo memset + float4 interior with shift indexing.
// ---------------------------------------------------------------------------
__global__ void __launch_bounds__(256) dw_kernel(const float* __restrict__ x) {
    int bc = blockIdx.y;
    int rowBase = blockIdx.x * 32;
    const float4* xp4 = (const float4*)(x + (size_t)bc * 4096);

    __shared__ __align__(16) float s[38 * 70];
    __shared__ __align__(16) float wsh2[56];     // 7 rows padded to 8

    int tid = threadIdx.x;
    if (tid < 56) {
        int r = tid >> 3, c = tid & 7;
        wsh2[tid] = (c < 7) ? g_fused[bc * 49 + r * 7 + c] : 0.f;
    }
    // halo columns are always outside the 64-wide image -> zero
    if (tid < 228) {
        int r = tid / 6, h = tid - r * 6;
        int col = (h < 3) ? h : (h + 64);        // 0,1,2, 67,68,69
        s[r * 70 + col] = 0.f;
    }
    // interior: 38 rows x 16 float4, shift indexing, row-range predicate only
    #pragma unroll
    for (int j = 0; j < 3; j++) {
        int idx = tid + j * 256;
        if (idx < 608) {
            int r = idx >> 4, c4 = idx & 15;
            int gr = rowBase + r - 3;
            float4 v = (gr >= 0 && gr < 64) ? xp4[gr * 16 + c4]
                                            : make_float4(0.f, 0.f, 0.f, 0.f);
            float* d = s + r * 70 + 3 + c4 * 4;
            d[0] = v.x; d[1] = v.y; d[2] = v.z; d[3] = v.w;
        }
    }
    __syncthreads();

    const int c0  = (tid & 15) * 4;              // output cols c0..c0+3
    const int lr0 = (tid >> 4) * 2;              // local output rows lr0, lr0+1

    float acc0[4] = {0.f, 0.f, 0.f, 0.f};
    float acc1[4] = {0.f, 0.f, 0.f, 0.f};
    float wbuf[2][8];

    #pragma unroll
    for (int r = 0; r < 8; r++) {                // smem rows lr0+r
        float v[10];
        const float* row = s + (lr0 + r) * 70 + c0;
        #pragma unroll
        for (int q = 0; q < 5; q++) *(float2*)&v[q * 2] = *(const float2*)(row + q * 2);

        if (r < 7) {                             // weight row r -> wbuf[r&1]
            *(float4*)&wbuf[r & 1][0] = *(const float4*)&wsh2[r * 8];
            *(float4*)&wbuf[r & 1][4] = *(const float4*)&wsh2[r * 8 + 4];
        }
        if (r <= 6) {                            // out row lr0, ky = r
            #pragma unroll
            for (int kx = 0; kx < 7; kx++) {
                float wv = wbuf[r & 1][kx];
                #pragma unroll
                for (int c = 0; c < 4; c++) acc0[c] += v[kx + c] * wv;
            }
        }
        if (r >= 1) {                            // out row lr0+1, ky = r-1
            #pragma unroll
            for (int kx = 0; kx < 7; kx++) {
                float wv = wbuf[(r - 1) & 1][kx];
                #pragma unroll
                for (int c = 0; c < 4; c++) acc1[c] += v[kx + c] * wv;
            }
        }
    }

    uint32_t base = (uint32_t)bc * 4096u + (uint32_t)(rowBase + lr0) * 64u + (uint32_t)c0;
    {
        __half2 ha, hb;
        ha.x = __float2half_rn(acc0[0]); ha.y = __float2half_rn(acc0[1]);
        hb.x = __float2half_rn(acc0[2]); hb.y = __float2half_rn(acc0[3]);
        uint2 st; st.x = *(uint32_t*)&ha; st.y = *(uint32_t*)&hb;
        *(uint2*)&g_bh[base] = st;
    }
    {
        __half2 ha, hb;
        ha.x = __float2half_rn(acc1[0]); ha.y = __float2half_rn(acc1[1]);
        hb.x = __float2half_rn(acc1[2]); hb.y = __float2half_rn(acc1[3]);
        uint2 st; st.x = *(uint32_t*)&ha; st.y = *(uint32_t*)&hb;
        *(uint2*)&g_bh[base + 64] = st;
    }
}

// ---------------------------------------------------------------------------
// Kernel 5: pointwise GEMM via mma.sync fp16 single pass, 3-stage cp.async.
//   Stage (18432 B): A[128x80B] @0, B[32x256B] @10240.  (exact R11 version)
// ---------------------------------------------------------------------------
__global__ void __launch_bounds__(256) pw_gemm_mma(float* __restrict__ out) {
    extern __shared__ __align__(128) char sm[];
    const uint32_t smb = smem_u32(sm);
    const uint32_t STAGE = 18432;

    const int tid = threadIdx.x;
    const int wid = tid >> 5, lane = tid & 31;
    const int warp_m = wid & 1;
    const int warp_n = wid >> 1;
    const int n0 = blockIdx.x * 128;
    const int m0 = blockIdx.y * 128;
    const int b  = blockIdx.z;

    float acc[4][4][4];
    #pragma unroll
    for (int i = 0; i < 4; i++)
        #pragma unroll
        for (int j = 0; j < 4; j++)
            #pragma unroll
            for (int q = 0; q < 4; q++) acc[i][j][q] = 0.f;

    const int lm16 = lane & 15, lhi = lane >> 4;
    const uint32_t aRowOff = (uint32_t)(warp_m * 64 + lm16) * 80 + (uint32_t)lhi * 16;
    const int bN = warp_n * 32 + lhi * 8;

    float* ob = out + (size_t)b * 1048576;

    auto issue = [&](int kc, uint32_t sbase) {
        #pragma unroll
        for (int i = 0; i < 2; i++) {
            int lin = tid + i * 256;
            int r = lin >> 2, j = lin & 3;
            const __half* src = g_pwh + (size_t)(m0 + r) * 256 + kc * 32 + j * 8;
            cp16(sbase + r * 80 + j * 16, src);
        }
        #pragma unroll
        for (int i = 0; i < 2; i++) {
            int lin = tid + i * 256;
            int k = lin >> 4, j16 = lin & 15;
            const __half* src = g_bh + (size_t)b * 1048576
                + (size_t)(kc * 32 + k) * 4096 + n0 + j16 * 8;
            cp16(sbase + 10240 + (uint32_t)k * 256
                 + (uint32_t)((j16 ^ (k & 7)) * 16), src);
        }
        cp_commit();
    };

    issue(0, smb);
    issue(1, smb + STAGE);

    for (int kc = 0; kc < 8; kc++) {
        const uint32_t sbase = smb + (uint32_t)(kc % 3) * STAGE;
        if (kc == 7) cp_wait0(); else cp_wait1();
        __syncthreads();
        if (kc < 6) issue(kc + 2, smb + (uint32_t)((kc + 2) % 3) * STAGE);

        const uint32_t aB = sbase, bB = sbase + 10240;
        #pragma unroll
        for (int ks = 0; ks < 2; ks++) {
            uint32_t bf[2][4];
            #pragma unroll
            for (int p = 0; p < 2; p++) {
                int k = ks * 16 + lm16;
                int n = bN + p * 16;
                uint32_t off = (uint32_t)k * 256
                             + (uint32_t)(((n >> 3) ^ (k & 7)) * 16);
                ldsm_x4_t(bf[p], bB + off);
            }
            uint32_t af[4][4];
            #pragma unroll
            for (int mi = 0; mi < 4; mi++)
                ldsm_x4(af[mi], aB + aRowOff + (uint32_t)mi * (16 * 80)
                               + (uint32_t)ks * 32);
            #pragma unroll
            for (int mi = 0; mi < 4; mi++) {
                #pragma unroll
                for (int p = 0; p < 2; p++) {
                    mma_f16(acc[mi][2 * p],     af[mi], &bf[p][0]);
                    mma_f16(acc[mi][2 * p + 1], af[mi], &bf[p][2]);
                }
            }
        }
    }

    const int rowBase = m0 + warp_m * 64 + (lane >> 2);
    const int colBase = n0 + warp_n * 32 + (lane & 3) * 2;
    #pragma unroll
    for (int mi = 0; mi < 4; mi++) {
        #pragma unroll
        for (int ni = 0; ni < 4; ni++) {
            int r = rowBase + mi * 16;
            int c = colBase + ni * 8;
            *(float2*)&ob[(size_t)r * 4096 + c] =
                make_float2(acc[mi][ni][0], acc[mi][ni][1]);
            *(float2*)&ob[(size_t)(r + 8) * 4096 + c] =
                make_float2(acc[mi][ni][2], acc[mi][ni][3]);
        }
    }
}

// ---------------------------------------------------------------------------
// launch
// ---------------------------------------------------------------------------
extern "C" void kernel_launch(void* const* d_in, const int* in_sizes, int n_in,
                              void* d_out, int out_size) {
    const float* x   = (const float*)d_in[0];  // [16,256,64,64]
    const float* dw  = (const float*)d_in[1];  // [256,1,7,7]
    const float* pwm = (const float*)d_in[2];  // [256,256]
    const float* w1  = (const float*)d_in[3];  // [64,256]
    const float* b1  = (const float*)d_in[4];  // [64]
    const float* w2  = (const float*)d_in[5];  // [12544,64]
    const float* b2  = (const float*)d_in[6];  // [12544]
    float* out = (float*)d_out;                // [16,256,64,64] fp32

    cudaFuncSetAttribute(pw_gemm_mma, cudaFuncAttributeMaxDynamicSharedMemorySize, 55296);

    pool_kernel<<<4096, 256>>>(x, pwm);
    mlp1_kernel<<<16, 64>>>(w1, b1);
    fuse_kernel<<<dim3(98, 2), 256>>>(dw, w2, b2);
    dw_kernel<<<dim3(2, 4096), 256>>>(x);
    pw_gemm_mma<<<dim3(32, 2, 16), 256, 55296>>>(out);
}

// round 15
// speedup vs baseline: 1.4648x; 1.0949x over previous
#include <cuda_runtime.h>
#include <cuda_fp16.h>
#include <math.h>
#include <stdint.h>

#define DINLINE __device__ __forceinline__

// Problem constants: B=16, C=256, H=W=64, K=7, C/4=64, C*K*K=12544

// ---- scratch (static device allocations: allowed) ----
__device__ __align__(128) float g_pooled[16 * 256];            // [B, C]
__device__ __align__(128) float g_h[16 * 64];                  // [B, C/4]
__device__ __align__(128) float g_fused[16 * 256 * 49];        // [B, C, 49]
__device__ __align__(128) __half g_bh[16u*256u*64u*64u];       // dw out, fp16 (32 MB)
__device__ __align__(128) __half g_pwh[256 * 256];             // fp16 pw weights

// ===========================================================================
// PTX helpers (all legal on plain sm_100 target)
// ===========================================================================
DINLINE uint32_t smem_u32(const void* p) {
    uint32_t a;
    asm("{ .reg .u64 t; cvta.to.shared.u64 t, %1; cvt.u32.u64 %0, t; }" : "=r"(a) : "l"(p));
    return a;
}
DINLINE void ldsm_x4(uint32_t* r, uint32_t addr) {
    asm volatile("ldmatrix.sync.aligned.m8n8.x4.shared.b16 {%0,%1,%2,%3}, [%4];"
                 : "=r"(r[0]), "=r"(r[1]), "=r"(r[2]), "=r"(r[3]) : "r"(addr));
}
DINLINE void ldsm_x4_t(uint32_t* r, uint32_t addr) {
    asm volatile("ldmatrix.sync.aligned.m8n8.x4.trans.shared.b16 {%0,%1,%2,%3}, [%4];"
                 : "=r"(r[0]), "=r"(r[1]), "=r"(r[2]), "=r"(r[3]) : "r"(addr));
}
DINLINE void mma_f16(float* d, const uint32_t* a, const uint32_t* b) {
    asm volatile(
        "mma.sync.aligned.m16n8k16.row.col.f32.f16.f16.f32 "
        "{%0,%1,%2,%3}, {%4,%5,%6,%7}, {%8,%9}, {%0,%1,%2,%3};"
        : "+f"(d[0]), "+f"(d[1]), "+f"(d[2]), "+f"(d[3])
        : "r"(a[0]), "r"(a[1]), "r"(a[2]), "r"(a[3]), "r"(b[0]), "r"(b[1]));
}
DINLINE void cp16(uint32_t dst, const void* src) {
    asm volatile("cp.async.cg.shared.global [%0], [%1], 16;"
                 :: "r"(dst), "l"(__cvta_generic_to_global(src)));
}
DINLINE void cp_commit() { asm volatile("cp.async.commit_group;" ::: "memory"); }
DINLINE void cp_wait0()  { asm volatile("cp.async.wait_group 0;" ::: "memory"); }
DINLINE void cp_wait1()  { asm volatile("cp.async.wait_group 1;" ::: "memory"); }

// ---------------------------------------------------------------------------
// Kernel 1: global average pool (+ pw fp16 convert folded into first 256 blocks)
// ---------------------------------------------------------------------------
__global__ void pool_kernel(const float* __restrict__ x, const float* __restrict__ pw) {
    int bc = blockIdx.x;
    if (bc < 256) {
        int i = bc * 256 + threadIdx.x;
        g_pwh[i] = __float2half_rn(pw[i]);
    }
    const float4* xp = (const float4*)(x + (size_t)bc * 4096);
    float s = 0.f;
    #pragma unroll 4
    for (int i = threadIdx.x; i < 1024; i += 256) {
        float4 v = xp[i];
        s += (v.x + v.y) + (v.z + v.w);
    }
    __shared__ float red[256];
    red[threadIdx.x] = s;
    __syncthreads();
    for (int off = 128; off > 0; off >>= 1) {
        if (threadIdx.x < off) red[threadIdx.x] += red[threadIdx.x + off];
        __syncthreads();
    }
    if (threadIdx.x == 0) g_pooled[bc] = red[0] * (1.f / 4096.f);
}

// ---------------------------------------------------------------------------
// Kernel 2: h = gelu(pooled @ w1^T + b1)
// ---------------------------------------------------------------------------
__global__ void mlp1_kernel(const float* __restrict__ w1, const float* __restrict__ b1) {
    int b = blockIdx.x;
    int j = threadIdx.x;   // 0..63
    __shared__ float p[256];
    for (int i = threadIdx.x; i < 256; i += 64) p[i] = g_pooled[b * 256 + i];
    __syncthreads();
    float s = b1[j];
    const float* wr = w1 + (size_t)j * 256;
    #pragma unroll 8
    for (int c = 0; c < 256; c++) s += p[c] * wr[c];
    g_h[b * 64 + j] = 0.5f * s * (1.0f + erff(s * 0.70710678118654752f));
}

// ---------------------------------------------------------------------------
// Kernel 3: fused[b,wi] = dw[wi] + b2[wi] + sum_j h[b,j]*w2[wi,j]
// ---------------------------------------------------------------------------
__global__ void __launch_bounds__(256) fuse_kernel(const float* __restrict__ dw,
                                                   const float* __restrict__ w2,
                                                   const float* __restrict__ b2) {
    __shared__ float hs[8 * 64];
    __shared__ float w2s[128 * 68];
    int tid = threadIdx.x;
    int wi0 = blockIdx.x * 128;
    int b0 = blockIdx.y * 8;

    if (tid < 128) *(float4*)(hs + tid * 4) = *(const float4*)(g_h + b0 * 64 + tid * 4);
    #pragma unroll
    for (int i = 0; i < 8; i++) {
        int lin = tid + i * 256;
        int r = lin >> 4, j4 = lin & 15;
        float4 v = *(const float4*)(w2 + (size_t)(wi0 + r) * 64 + j4 * 4);
        *(float4*)(w2s + r * 68 + j4 * 4) = v;
    }
    __syncthreads();

    int wiL = tid & 127;
    int bg = (tid >> 7) * 4;
    int wi = wi0 + wiL;
    float base = dw[wi] + b2[wi];
    float acc[4];
    #pragma unroll
    for (int bb = 0; bb < 4; bb++) acc[bb] = base;

    const float* wr = w2s + wiL * 68;
    #pragma unroll
    for (int j4 = 0; j4 < 16; j4++) {
        float4 w = *(const float4*)(wr + j4 * 4);
        #pragma unroll
        for (int bb = 0; bb < 4; bb++) {
            float4 h = *(const float4*)(hs + (bg + bb) * 64 + j4 * 4);
            acc[bb] += w.x * h.x + w.y * h.y + w.z * h.z + w.w * h.w;
        }
    }
    #pragma unroll
    for (int bb = 0; bb < 4; bb++)
        g_fused[(size_t)(b0 + bg + bb) * 12544 + wi] = acc[bb];
}

// ---------------------------------------------------------------------------
// Kernel 4 v4: per-sample depthwise 7x7 conv, pad=3.
// ONE block per (b,c): whole 64x64 image.  Thread = 4 rows x 4 cols.
// smem tile 70 rows x 72-float pitch (every row 16B aligned -> LDS.128 reads).
// 4-row rotating weight buffer, statically indexed.
// ---------------------------------------------------------------------------
__global__ void __launch_bounds__(256) dw_kernel(const float* __restrict__ x) {
    int bc = blockIdx.x;
    const float4* xp4 = (const float4*)(x + (size_t)bc * 4096);

    __shared__ __align__(16) float s[70 * 72];   // image at rows 3..66, cols 3..66
    __shared__ __align__(16) float wsh[56];      // 7 rows padded to 8

    int tid = threadIdx.x;
    if (tid < 56) {
        int r = tid >> 3, c = tid & 7;
        wsh[tid] = (c < 7) ? g_fused[bc * 49 + r * 7 + c] : 0.f;
    }
    // zero halo rows 0-2 and 67-69 (cols 0..69)
    #pragma unroll
    for (int i = tid; i < 420; i += 256) {
        int r = i / 70, c = i - r * 70;
        int rr = (r < 3) ? r : r + 64;
        s[rr * 72 + c] = 0.f;
    }
    // zero side cols {0,1,2,67,68,69} for rows 3..66
    #pragma unroll
    for (int i = tid; i < 384; i += 256) {
        int r = i / 6, h = i - r * 6;
        int col = (h < 3) ? h : h + 64;
        s[(r + 3) * 72 + col] = 0.f;
    }
    // interior: 1024 float4 loads, 4/thread, no predicates
    #pragma unroll
    for (int j = 0; j < 4; j++) {
        int idx = tid + j * 256;                 // == r*16 + c4
        int r = idx >> 4, c4 = idx & 15;
        float4 v = xp4[idx];
        float* d = s + (r + 3) * 72 + 3 + c4 * 4;
        d[0] = v.x; d[1] = v.y; d[2] = v.z; d[3] = v.w;
    }
    __syncthreads();

    const int c0 = (tid & 15) * 4;               // output cols c0..c0+3
    const int r0 = (tid >> 4) * 4;               // output rows r0..r0+3

    float acc[4][4];
    #pragma unroll
    for (int dy = 0; dy < 4; dy++)
        #pragma unroll
        for (int c = 0; c < 4; c++) acc[dy][c] = 0.f;
    float wbuf[4][8];

    #pragma unroll
    for (int r = 0; r < 10; r++) {               // smem rows r0+r
        float v[10];
        const float* row = s + (r0 + r) * 72 + c0;   // 16B aligned
        *(float4*)&v[0] = *(const float4*)(row);
        *(float4*)&v[4] = *(const float4*)(row + 4);
        *(float2*)&v[8] = *(const float2*)(row + 8);

        if (r < 7) {                             // weight row r -> wbuf[r&3]
            *(float4*)&wbuf[r & 3][0] = *(const float4*)&wsh[r * 8];
            *(float4*)&wbuf[r & 3][4] = *(const float4*)&wsh[r * 8 + 4];
        }
        #pragma unroll
        for (int dy = 0; dy < 4; dy++) {
            int ky = r - dy;
            if (ky >= 0 && ky < 7) {
                #pragma unroll
                for (int kx = 0; kx < 7; kx++) {
                    float wv = wbuf[ky & 3][kx];
                    #pragma unroll
                    for (int c = 0; c < 4; c++) acc[dy][c] += v[kx + c] * wv;
                }
            }
        }
    }

    uint32_t base = (uint32_t)bc * 4096u + (uint32_t)r0 * 64u + (uint32_t)c0;
    #pragma unroll
    for (int dy = 0; dy < 4; dy++) {
        __half2 ha, hb;
        ha.x = __float2half_rn(acc[dy][0]); ha.y = __float2half_rn(acc[dy][1]);
        hb.x = __float2half_rn(acc[dy][2]); hb.y = __float2half_rn(acc[dy][3]);
        uint2 st; st.x = *(uint32_t*)&ha; st.y = *(uint32_t*)&hb;
        *(uint2*)&g_bh[base + dy * 64u] = st;
    }
}

// ---------------------------------------------------------------------------
// Kernel 5: pointwise GEMM via mma.sync fp16 single pass, 3-stage cp.async.
//   Stage (18432 B): A[128x80B] @0, B[32x256B] @10240.  (unchanged R14)
// ---------------------------------------------------------------------------
__global__ void __launch_bounds__(256) pw_gemm_mma(float* __restrict__ out) {
    extern __shared__ __align__(128) char sm[];
    const uint32_t smb = smem_u32(sm);
    const uint32_t STAGE = 18432;

    const int tid = threadIdx.x;
    const int wid = tid >> 5, lane = tid & 31;
    const int warp_m = wid & 1;
    const int warp_n = wid >> 1;
    const int n0 = blockIdx.x * 128;
    const int m0 = blockIdx.y * 128;
    const int b  = blockIdx.z;

    float acc[4][4][4];
    #pragma unroll
    for (int i = 0; i < 4; i++)
        #pragma unroll
        for (int j = 0; j < 4; j++)
            #pragma unroll
            for (int q = 0; q < 4; q++) acc[i][j][q] = 0.f;

    const int lm16 = lane & 15, lhi = lane >> 4;
    const uint32_t aRowOff = (uint32_t)(warp_m * 64 + lm16) * 80 + (uint32_t)lhi * 16;
    const int bN = warp_n * 32 + lhi * 8;

    float* ob = out + (size_t)b * 1048576;

    auto issue = [&](int kc, uint32_t sbase) {
        #pragma unroll
        for (int i = 0; i < 2; i++) {
            int lin = tid + i * 256;
            int r = lin >> 2, j = lin & 3;
            const __half* src = g_pwh + (size_t)(m0 + r) * 256 + kc * 32 + j * 8;
            cp16(sbase + r * 80 + j * 16, src);
        }
        #pragma unroll
        for (int i = 0; i < 2; i++) {
            int lin = tid + i * 256;
            int k = lin >> 4, j16 = lin & 15;
            const __half* src = g_bh + (size_t)b * 1048576
                + (size_t)(kc * 32 + k) * 4096 + n0 + j16 * 8;
            cp16(sbase + 10240 + (uint32_t)k * 256
                 + (uint32_t)((j16 ^ (k & 7)) * 16), src);
        }
        cp_commit();
    };

    issue(0, smb);
    issue(1, smb + STAGE);

    for (int kc = 0; kc < 8; kc++) {
        const uint32_t sbase = smb + (uint32_t)(kc % 3) * STAGE;
        if (kc == 7) cp_wait0(); else cp_wait1();
        __syncthreads();
        if (kc < 6) issue(kc + 2, smb + (uint32_t)((kc + 2) % 3) * STAGE);

        const uint32_t aB = sbase, bB = sbase + 10240;
        #pragma unroll
        for (int ks = 0; ks < 2; ks++) {
            uint32_t bf[2][4];
            #pragma unroll
            for (int p = 0; p < 2; p++) {
                int k = ks * 16 + lm16;
                int n = bN + p * 16;
                uint32_t off = (uint32_t)k * 256
                             + (uint32_t)(((n >> 3) ^ (k & 7)) * 16);
                ldsm_x4_t(bf[p], bB + off);
            }
            uint32_t af[4][4];
            #pragma unroll
            for (int mi = 0; mi < 4; mi++)
                ldsm_x4(af[mi], aB + aRowOff + (uint32_t)mi * (16 * 80)
                               + (uint32_t)ks * 32);
            #pragma unroll
            for (int mi = 0; mi < 4; mi++) {
                #pragma unroll
                for (int p = 0; p < 2; p++) {
                    mma_f16(acc[mi][2 * p],     af[mi], &bf[p][0]);
                    mma_f16(acc[mi][2 * p + 1], af[mi], &bf[p][2]);
                }
            }
        }
    }

    const int rowBase = m0 + warp_m * 64 + (lane >> 2);
    const int colBase = n0 + warp_n * 32 + (lane & 3) * 2;
    #pragma unroll
    for (int mi = 0; mi < 4; mi++) {
        #pragma unroll
        for (int ni = 0; ni < 4; ni++) {
            int r = rowBase + mi * 16;
            int c = colBase + ni * 8;
            *(float2*)&ob[(size_t)r * 4096 + c] =
                make_float2(acc[mi][ni][0], acc[mi][ni][1]);
            *(float2*)&ob[(size_t)(r + 8) * 4096 + c] =
                make_float2(acc[mi][ni][2], acc[mi][ni][3]);
        }
    }
}

// ---------------------------------------------------------------------------
// launch
// ---------------------------------------------------------------------------
extern "C" void kernel_launch(void* const* d_in, const int* in_sizes, int n_in,
                              void* d_out, int out_size) {
    const float* x   = (const float*)d_in[0];  // [16,256,64,64]
    const float* dw  = (const float*)d_in[1];  // [256,1,7,7]
    const float* pwm = (const float*)d_in[2];  // [256,256]
    const float* w1  = (const float*)d_in[3];  // [64,256]
    const float* b1  = (const float*)d_in[4];  // [64]
    const float* w2  = (const float*)d_in[5];  // [12544,64]
    const float* b2  = (const float*)d_in[6];  // [12544]
    float* out = (float*)d_out;                // [16,256,64,64] fp32

    cudaFuncSetAttribute(pw_gemm_mma, cudaFuncAttributeMaxDynamicSharedMemorySize, 55296);

    pool_kernel<<<4096, 256>>>(x, pwm);
    mlp1_kernel<<<16, 64>>>(w1, b1);
    fuse_kernel<<<dim3(98, 2), 256>>>(dw, w2, b2);
    dw_kernel<<<4096, 256>>>(x);
    pw_gemm_mma<<<dim3(32, 2, 16), 256, 55296>>>(out);
}

// round 16
// speedup vs baseline: 1.4678x; 1.0020x over previous
#include <cuda_runtime.h>
#include <cuda_fp16.h>
#include <math.h>
#include <stdint.h>

#define DINLINE __device__ __forceinline__

// Problem constants: B=16, C=256, H=W=64, K=7, C/4=64, C*K*K=12544

// ---- scratch (static device allocations: allowed) ----
__device__ __align__(128) float g_pooled[16 * 256];            // [B, C]
__device__ __align__(128) float g_h[16 * 64];                  // [B, C/4]
__device__ __align__(128) float g_fused[16 * 256 * 49];        // [B, C, 49]
__device__ __align__(128) __half g_bh[16u*256u*64u*64u];       // dw out, fp16 (32 MB)
__device__ __align__(128) __half g_pwh[256 * 256];             // fp16 pw weights

// ===========================================================================
// PTX helpers (all legal on plain sm_100 target)
// ===========================================================================
DINLINE uint32_t smem_u32(const void* p) {
    uint32_t a;
    asm("{ .reg .u64 t; cvta.to.shared.u64 t, %1; cvt.u32.u64 %0, t; }" : "=r"(a) : "l"(p));
    return a;
}
DINLINE void ldsm_x4(uint32_t* r, uint32_t addr) {
    asm volatile("ldmatrix.sync.aligned.m8n8.x4.shared.b16 {%0,%1,%2,%3}, [%4];"
                 : "=r"(r[0]), "=r"(r[1]), "=r"(r[2]), "=r"(r[3]) : "r"(addr));
}
DINLINE void ldsm_x4_t(uint32_t* r, uint32_t addr) {
    asm volatile("ldmatrix.sync.aligned.m8n8.x4.trans.shared.b16 {%0,%1,%2,%3}, [%4];"
                 : "=r"(r[0]), "=r"(r[1]), "=r"(r[2]), "=r"(r[3]) : "r"(addr));
}
DINLINE void mma_f16(float* d, const uint32_t* a, const uint32_t* b) {
    asm volatile(
        "mma.sync.aligned.m16n8k16.row.col.f32.f16.f16.f32 "
        "{%0,%1,%2,%3}, {%4,%5,%6,%7}, {%8,%9}, {%0,%1,%2,%3};"
        : "+f"(d[0]), "+f"(d[1]), "+f"(d[2]), "+f"(d[3])
        : "r"(a[0]), "r"(a[1]), "r"(a[2]), "r"(a[3]), "r"(b[0]), "r"(b[1]));
}
DINLINE void cp16(uint32_t dst, const void* src) {
    asm volatile("cp.async.cg.shared.global [%0], [%1], 16;"
                 :: "r"(dst), "l"(__cvta_generic_to_global(src)));
}
DINLINE void cp_commit() { asm volatile("cp.async.commit_group;" ::: "memory"); }
DINLINE void cp_wait0()  { asm volatile("cp.async.wait_group 0;" ::: "memory"); }
DINLINE void cp_wait1()  { asm volatile("cp.async.wait_group 1;" ::: "memory"); }

// ---------------------------------------------------------------------------
// Kernel 1: global average pool (+ pw fp16 convert folded into first 256 blocks)
// ---------------------------------------------------------------------------
__global__ void pool_kernel(const float* __restrict__ x, const float* __restrict__ pw) {
    int bc = blockIdx.x;
    if (bc < 256) {
        int i = bc * 256 + threadIdx.x;
        g_pwh[i] = __float2half_rn(pw[i]);
    }
    const float4* xp = (const float4*)(x + (size_t)bc * 4096);
    float s = 0.f;
    #pragma unroll 4
    for (int i = threadIdx.x; i < 1024; i += 256) {
        float4 v = xp[i];
        s += (v.x + v.y) + (v.z + v.w);
    }
    __shared__ float red[256];
    red[threadIdx.x] = s;
    __syncthreads();
    for (int off = 128; off > 0; off >>= 1) {
        if (threadIdx.x < off) red[threadIdx.x] += red[threadIdx.x + off];
        __syncthreads();
    }
    if (threadIdx.x == 0) g_pooled[bc] = red[0] * (1.f / 4096.f);
}

// ---------------------------------------------------------------------------
// Kernel 2: h = gelu(pooled @ w1^T + b1)
// ---------------------------------------------------------------------------
__global__ void mlp1_kernel(const float* __restrict__ w1, const float* __restrict__ b1) {
    int b = blockIdx.x;
    int j = threadIdx.x;   // 0..63
    __shared__ float p[256];
    for (int i = threadIdx.x; i < 256; i += 64) p[i] = g_pooled[b * 256 + i];
    __syncthreads();
    float s = b1[j];
    const float* wr = w1 + (size_t)j * 256;
    #pragma unroll 8
    for (int c = 0; c < 256; c++) s += p[c] * wr[c];
    g_h[b * 64 + j] = 0.5f * s * (1.0f + erff(s * 0.70710678118654752f));
}

// ---------------------------------------------------------------------------
// Kernel 3: fused[b,wi] = dw[wi] + b2[wi] + sum_j h[b,j]*w2[wi,j]
// ---------------------------------------------------------------------------
__global__ void __launch_bounds__(256) fuse_kernel(const float* __restrict__ dw,
                                                   const float* __restrict__ w2,
                                                   const float* __restrict__ b2) {
    __shared__ float hs[8 * 64];
    __shared__ float w2s[128 * 68];
    int tid = threadIdx.x;
    int wi0 = blockIdx.x * 128;
    int b0 = blockIdx.y * 8;

    if (tid < 128) *(float4*)(hs + tid * 4) = *(const float4*)(g_h + b0 * 64 + tid * 4);
    #pragma unroll
    for (int i = 0; i < 8; i++) {
        int lin = tid + i * 256;
        int r = lin >> 4, j4 = lin & 15;
        float4 v = *(const float4*)(w2 + (size_t)(wi0 + r) * 64 + j4 * 4);
        *(float4*)(w2s + r * 68 + j4 * 4) = v;
    }
    __syncthreads();

    int wiL = tid & 127;
    int bg = (tid >> 7) * 4;
    int wi = wi0 + wiL;
    float base = dw[wi] + b2[wi];
    float acc[4];
    #pragma unroll
    for (int bb = 0; bb < 4; bb++) acc[bb] = base;

    const float* wr = w2s + wiL * 68;
    #pragma unroll
    for (int j4 = 0; j4 < 16; j4++) {
        float4 w = *(const float4*)(wr + j4 * 4);
        #pragma unroll
        for (int bb = 0; bb < 4; bb++) {
            float4 h = *(const float4*)(hs + (bg + bb) * 64 + j4 * 4);
            acc[bb] += w.x * h.x + w.y * h.y + w.z * h.z + w.w * h.w;
        }
    }
    #pragma unroll
    for (int bb = 0; bb < 4; bb++)
        g_fused[(size_t)(b0 + bg + bb) * 12544 + wi] = acc[bb];
}

// ---------------------------------------------------------------------------
// Kernel 4 v4: per-sample depthwise 7x7 conv, pad=3.  (unchanged R15 winner)
// ONE block per (b,c): whole 64x64 image.  Thread = 4 rows x 4 cols.
// ---------------------------------------------------------------------------
__global__ void __launch_bounds__(256) dw_kernel(const float* __restrict__ x) {
    int bc = blockIdx.x;
    const float4* xp4 = (const float4*)(x + (size_t)bc * 4096);

    __shared__ __align__(16) float s[70 * 72];   // image at rows 3..66, cols 3..66
    __shared__ __align__(16) float wsh[56];      // 7 rows padded to 8

    int tid = threadIdx.x;
    if (tid < 56) {
        int r = tid >> 3, c = tid & 7;
        wsh[tid] = (c < 7) ? g_fused[bc * 49 + r * 7 + c] : 0.f;
    }
    #pragma unroll
    for (int i = tid; i < 420; i += 256) {
        int r = i / 70, c = i - r * 70;
        int rr = (r < 3) ? r : r + 64;
        s[rr * 72 + c] = 0.f;
    }
    #pragma unroll
    for (int i = tid; i < 384; i += 256) {
        int r = i / 6, h = i - r * 6;
        int col = (h < 3) ? h : h + 64;
        s[(r + 3) * 72 + col] = 0.f;
    }
    #pragma unroll
    for (int j = 0; j < 4; j++) {
        int idx = tid + j * 256;
        int r = idx >> 4, c4 = idx & 15;
        float4 v = xp4[idx];
        float* d = s + (r + 3) * 72 + 3 + c4 * 4;
        d[0] = v.x; d[1] = v.y; d[2] = v.z; d[3] = v.w;
    }
    __syncthreads();

    const int c0 = (tid & 15) * 4;
    const int r0 = (tid >> 4) * 4;

    float acc[4][4];
    #pragma unroll
    for (int dy = 0; dy < 4; dy++)
        #pragma unroll
        for (int c = 0; c < 4; c++) acc[dy][c] = 0.f;
    float wbuf[4][8];

    #pragma unroll
    for (int r = 0; r < 10; r++) {
        float v[10];
        const float* row = s + (r0 + r) * 72 + c0;
        *(float4*)&v[0] = *(const float4*)(row);
        *(float4*)&v[4] = *(const float4*)(row + 4);
        *(float2*)&v[8] = *(const float2*)(row + 8);

        if (r < 7) {
            *(float4*)&wbuf[r & 3][0] = *(const float4*)&wsh[r * 8];
            *(float4*)&wbuf[r & 3][4] = *(const float4*)&wsh[r * 8 + 4];
        }
        #pragma unroll
        for (int dy = 0; dy < 4; dy++) {
            int ky = r - dy;
            if (ky >= 0 && ky < 7) {
                #pragma unroll
                for (int kx = 0; kx < 7; kx++) {
                    float wv = wbuf[ky & 3][kx];
                    #pragma unroll
                    for (int c = 0; c < 4; c++) acc[dy][c] += v[kx + c] * wv;
                }
            }
        }
    }

    uint32_t base = (uint32_t)bc * 4096u + (uint32_t)r0 * 64u + (uint32_t)c0;
    #pragma unroll
    for (int dy = 0; dy < 4; dy++) {
        __half2 ha, hb;
        ha.x = __float2half_rn(acc[dy][0]); ha.y = __float2half_rn(acc[dy][1]);
        hb.x = __float2half_rn(acc[dy][2]); hb.y = __float2half_rn(acc[dy][3]);
        uint2 st; st.x = *(uint32_t*)&ha; st.y = *(uint32_t*)&hb;
        *(uint2*)&g_bh[base + dy * 64u] = st;
    }
}

// ---------------------------------------------------------------------------
// Kernel 5: pointwise GEMM via mma.sync fp16 single pass, 3-stage cp.async.
//   Stage (18432 B): A[128x80B] @0, B[32x256B] @10240.
//   ONE CHANGE vs R15: __launch_bounds__(256, 2) -> 2 CTAs/SM (16 warps).
// ---------------------------------------------------------------------------
__global__ void __launch_bounds__(256, 2) pw_gemm_mma(float* __restrict__ out) {
    extern __shared__ __align__(128) char sm[];
    const uint32_t smb = smem_u32(sm);
    const uint32_t STAGE = 18432;

    const int tid = threadIdx.x;
    const int wid = tid >> 5, lane = tid & 31;
    const int warp_m = wid & 1;
    const int warp_n = wid >> 1;
    const int n0 = blockIdx.x * 128;
    const int m0 = blockIdx.y * 128;
    const int b  = blockIdx.z;

    float acc[4][4][4];
    #pragma unroll
    for (int i = 0; i < 4; i++)
        #pragma unroll
        for (int j = 0; j < 4; j++)
            #pragma unroll
            for (int q = 0; q < 4; q++) acc[i][j][q] = 0.f;

    const int lm16 = lane & 15, lhi = lane >> 4;
    const uint32_t aRowOff = (uint32_t)(warp_m * 64 + lm16) * 80 + (uint32_t)lhi * 16;
    const int bN = warp_n * 32 + lhi * 8;

    float* ob = out + (size_t)b * 1048576;

    auto issue = [&](int kc, uint32_t sbase) {
        #pragma unroll
        for (int i = 0; i < 2; i++) {
            int lin = tid + i * 256;
            int r = lin >> 2, j = lin & 3;
            const __half* src = g_pwh + (size_t)(m0 + r) * 256 + kc * 32 + j * 8;
            cp16(sbase + r * 80 + j * 16, src);
        }
        #pragma unroll
        for (int i = 0; i < 2; i++) {
            int lin = tid + i * 256;
            int k = lin >> 4, j16 = lin & 15;
            const __half* src = g_bh + (size_t)b * 1048576
                + (size_t)(kc * 32 + k) * 4096 + n0 + j16 * 8;
            cp16(sbase + 10240 + (uint32_t)k * 256
                 + (uint32_t)((j16 ^ (k & 7)) * 16), src);
        }
        cp_commit();
    };

    issue(0, smb);
    issue(1, smb + STAGE);

    for (int kc = 0; kc < 8; kc++) {
        const uint32_t sbase = smb + (uint32_t)(kc % 3) * STAGE;
        if (kc == 7) cp_wait0(); else cp_wait1();
        __syncthreads();
        if (kc < 6) issue(kc + 2, smb + (uint32_t)((kc + 2) % 3) * STAGE);

        const uint32_t aB = sbase, bB = sbase + 10240;
        #pragma unroll
        for (int ks = 0; ks < 2; ks++) {
            uint32_t bf[2][4];
            #pragma unroll
            for (int p = 0; p < 2; p++) {
                int k = ks * 16 + lm16;
                int n = bN + p * 16;
                uint32_t off = (uint32_t)k * 256
                             + (uint32_t)(((n >> 3) ^ (k & 7)) * 16);
                ldsm_x4_t(bf[p], bB + off);
            }
            uint32_t af[4][4];
            #pragma unroll
            for (int mi = 0; mi < 4; mi++)
                ldsm_x4(af[mi], aB + aRowOff + (uint32_t)mi * (16 * 80)
                               + (uint32_t)ks * 32);
            #pragma unroll
            for (int mi = 0; mi < 4; mi++) {
                #pragma unroll
                for (int p = 0; p < 2; p++) {
                    mma_f16(acc[mi][2 * p],     af[mi], &bf[p][0]);
                    mma_f16(acc[mi][2 * p + 1], af[mi], &bf[p][2]);
                }
            }
        }
    }

    const int rowBase = m0 + warp_m * 64 + (lane >> 2);
    const int colBase = n0 + warp_n * 32 + (lane & 3) * 2;
    #pragma unroll
    for (int mi = 0; mi < 4; mi++) {
        #pragma unroll
        for (int ni = 0; ni < 4; ni++) {
            int r = rowBase + mi * 16;
            int c = colBase + ni * 8;
            *(float2*)&ob[(size_t)r * 4096 + c] =
                make_float2(acc[mi][ni][0], acc[mi][ni][1]);
            *(float2*)&ob[(size_t)(r + 8) * 4096 + c] =
                make_float2(acc[mi][ni][2], acc[mi][ni][3]);
        }
    }
}

// ---------------------------------------------------------------------------
// launch
// ---------------------------------------------------------------------------
extern "C" void kernel_launch(void* const* d_in, const int* in_sizes, int n_in,
                              void* d_out, int out_size) {
    const float* x   = (const float*)d_in[0];  // [16,256,64,64]
    const float* dw  = (const float*)d_in[1];  // [256,1,7,7]
    const float* pwm = (const float*)d_in[2];  // [256,256]
    const float* w1  = (const float*)d_in[3];  // [64,256]
    const float* b1  = (const float*)d_in[4];  // [64]
    const float* w2  = (const float*)d_in[5];  // [12544,64]
    const float* b2  = (const float*)d_in[6];  // [12544]
    float* out = (float*)d_out;                // [16,256,64,64] fp32

    cudaFuncSetAttribute(pw_gemm_mma, cudaFuncAttributeMaxDynamicSharedMemorySize, 55296);

    pool_kernel<<<4096, 256>>>(x, pwm);
    mlp1_kernel<<<16, 64>>>(w1, b1);
    fuse_kernel<<<dim3(98, 2), 256>>>(dw, w2, b2);
    dw_kernel<<<4096, 256>>>(x);
    pw_gemm_mma<<<dim3(32, 2, 16), 256, 55296>>>(out);
}